// round 1
// baseline (speedup 1.0000x reference)
#include <cuda_runtime.h>
#include <cuda_bf16.h>
#include <stdint.h>

#define NB 2048      // anchors
#define NP 4         // positives per anchor
#define ND 256       // dim
#define NN 32768     // negatives
#define BM 128
#define BN 128
#define KC 32
#define SSTR 40      // padded smem row stride in bf16 (80 bytes, conflict-free for ldmatrix)
#define NYT (NN / BN)   // 256 n-tiles
#define INV_T 20.0f
#define SHIFT_C 28.853900817779268f  // 20 * log2(e)

// ---------------- scratch (static device globals; no allocation) ----------------
__device__ __nv_bfloat16 g_a[NB * ND];     // normalized anchors (bf16)
__device__ __nv_bfloat16 g_n[NN * ND];     // normalized negatives (bf16)
__device__ float g_pos[NB * NP];           // pos_sim (already / T)
__device__ float g_part[NB * NYT];         // per (anchor, n-tile) exp-sum partials
__device__ float g_lse[NB];                // neg logsumexp per anchor

// ---------------- helpers ----------------
__device__ __forceinline__ float wredsum(float v) {
#pragma unroll
    for (int o = 16; o; o >>= 1) v += __shfl_xor_sync(0xffffffffu, v, o);
    return v;
}

__device__ __forceinline__ float ex2(float x) {
    float y;
    asm("ex2.approx.f32 %0, %1;" : "=f"(y) : "f"(x));
    return y;
}

__device__ __forceinline__ void cpa16(void* sdst, const void* gsrc) {
    unsigned s = (unsigned)__cvta_generic_to_shared(sdst);
    asm volatile("cp.async.cg.shared.global [%0], [%1], 16;\n" :: "r"(s), "l"(gsrc));
}

__device__ __forceinline__ float logaddexp_(float x, float y) {
    float m = fmaxf(x, y);
    float d = fminf(x, y) - m;
    return m + log1pf(__expf(d));
}

// ---------------- kernel 1: normalize anchors (fp32->bf16) + fp32 pos_sim ----------------
__global__ void k_norm_anchor(const float* __restrict__ a, const float* __restrict__ p) {
    int w = (blockIdx.x * blockDim.x + threadIdx.x) >> 5;
    int lane = threadIdx.x & 31;
    if (w >= NB) return;

    const float4* ar = (const float4*)(a + (size_t)w * ND);
    float4 a0 = ar[lane], a1 = ar[lane + 32];
    float ss = a0.x*a0.x + a0.y*a0.y + a0.z*a0.z + a0.w*a0.w
             + a1.x*a1.x + a1.y*a1.y + a1.z*a1.z + a1.w*a1.w;
    ss = wredsum(ss);
    float inv = 1.0f / fmaxf(sqrtf(ss), 1e-12f);
    a0.x *= inv; a0.y *= inv; a0.z *= inv; a0.w *= inv;
    a1.x *= inv; a1.y *= inv; a1.z *= inv; a1.w *= inv;

    __nv_bfloat162* gr = (__nv_bfloat162*)(g_a + (size_t)w * ND);
    gr[2*lane]       = __floats2bfloat162_rn(a0.x, a0.y);
    gr[2*lane + 1]   = __floats2bfloat162_rn(a0.z, a0.w);
    gr[64 + 2*lane]  = __floats2bfloat162_rn(a1.x, a1.y);
    gr[64 + 2*lane+1]= __floats2bfloat162_rn(a1.z, a1.w);

#pragma unroll
    for (int j = 0; j < NP; j++) {
        const float4* pr = (const float4*)(p + (size_t)(w * NP + j) * ND);
        float4 p0 = pr[lane], p1 = pr[lane + 32];
        float ssp = p0.x*p0.x + p0.y*p0.y + p0.z*p0.z + p0.w*p0.w
                  + p1.x*p1.x + p1.y*p1.y + p1.z*p1.z + p1.w*p1.w;
        float dp  = a0.x*p0.x + a0.y*p0.y + a0.z*p0.z + a0.w*p0.w
                  + a1.x*p1.x + a1.y*p1.y + a1.z*p1.z + a1.w*p1.w;
        ssp = wredsum(ssp);
        dp  = wredsum(dp);
        if (lane == 0)
            g_pos[w * NP + j] = dp / fmaxf(sqrtf(ssp), 1e-12f) * INV_T;
    }
}

// ---------------- kernel 2: normalize negatives (fp32->bf16) ----------------
__global__ void k_norm_neg(const float* __restrict__ n) {
    int w = (blockIdx.x * blockDim.x + threadIdx.x) >> 5;
    int lane = threadIdx.x & 31;
    if (w >= NN) return;

    const float4* nr = (const float4*)(n + (size_t)w * ND);
    float4 v0 = nr[lane], v1 = nr[lane + 32];
    float ss = v0.x*v0.x + v0.y*v0.y + v0.z*v0.z + v0.w*v0.w
             + v1.x*v1.x + v1.y*v1.y + v1.z*v1.z + v1.w*v1.w;
    ss = wredsum(ss);
    float inv = 1.0f / fmaxf(sqrtf(ss), 1e-12f);

    __nv_bfloat162* gr = (__nv_bfloat162*)(g_n + (size_t)w * ND);
    gr[2*lane]        = __floats2bfloat162_rn(v0.x*inv, v0.y*inv);
    gr[2*lane + 1]    = __floats2bfloat162_rn(v0.z*inv, v0.w*inv);
    gr[64 + 2*lane]   = __floats2bfloat162_rn(v1.x*inv, v1.y*inv);
    gr[64 + 2*lane+1] = __floats2bfloat162_rn(v1.z*inv, v1.w*inv);
}

// ---------------- kernel 3: bf16 mma GEMM fused with exp-sum epilogue ----------------
// grid (NB/BM=16, NYT=256), 256 threads, warps 2(M) x 4(N), warp tile 64x32.
__global__ __launch_bounds__(256, 2) void k_gemm() {
    __shared__ __align__(16) __nv_bfloat16 sA[2][BM * SSTR];
    __shared__ __align__(16) __nv_bfloat16 sB[2][BN * SSTR];
    __shared__ float s_row[BM];

    const int tid = threadIdx.x;
    const int lane = tid & 31, warp = tid >> 5;
    const int wm = warp >> 2, wn = warp & 3;
    const int rowBase = blockIdx.x * BM;
    const int colBase = blockIdx.y * BN;
    if (tid < BM) s_row[tid] = 0.0f;

    float acc[4][4][4];
#pragma unroll
    for (int mi = 0; mi < 4; mi++)
#pragma unroll
        for (int ni = 0; ni < 4; ni++)
#pragma unroll
            for (int r = 0; r < 4; r++) acc[mi][ni][r] = 0.0f;

    // prologue: load chunk 0
    {
#pragma unroll
        for (int it = 0; it < 2; it++) {
            int c = tid + it * 256;
            int r = c >> 2, kk = (c & 3) << 3;
            cpa16(&sA[0][r * SSTR + kk], g_a + (size_t)(rowBase + r) * ND + kk);
            cpa16(&sB[0][r * SSTR + kk], g_n + (size_t)(colBase + r) * ND + kk);
        }
        asm volatile("cp.async.commit_group;\n");
    }

#pragma unroll 1
    for (int kc = 0; kc < ND / KC; kc++) {
        asm volatile("cp.async.wait_group 0;\n");
        __syncthreads();
        if (kc + 1 < ND / KC) {
            int k0 = (kc + 1) * KC;
            int buf = (kc + 1) & 1;
#pragma unroll
            for (int it = 0; it < 2; it++) {
                int c = tid + it * 256;
                int r = c >> 2, kk = (c & 3) << 3;
                cpa16(&sA[buf][r * SSTR + kk], g_a + (size_t)(rowBase + r) * ND + k0 + kk);
                cpa16(&sB[buf][r * SSTR + kk], g_n + (size_t)(colBase + r) * ND + k0 + kk);
            }
            asm volatile("cp.async.commit_group;\n");
        }

        const __nv_bfloat16* A  = sA[kc & 1];
        const __nv_bfloat16* Bm = sB[kc & 1];
#pragma unroll
        for (int ks = 0; ks < 2; ks++) {
            int koff = ks * 16;
            uint32_t af[4][4], bf[4][2];
#pragma unroll
            for (int mi = 0; mi < 4; mi++) {
                int r  = wm * 64 + mi * 16 + (lane & 15);
                int kk = koff + ((lane >> 4) << 3);
                unsigned ad = (unsigned)__cvta_generic_to_shared(A + r * SSTR + kk);
                asm volatile("ldmatrix.sync.aligned.m8n8.x4.shared.b16 {%0,%1,%2,%3}, [%4];\n"
                             : "=r"(af[mi][0]), "=r"(af[mi][1]), "=r"(af[mi][2]), "=r"(af[mi][3])
                             : "r"(ad));
            }
#pragma unroll
            for (int ni = 0; ni < 4; ni++) {
                int r  = wn * 32 + ni * 8 + (lane & 7);
                int kk = koff + (((lane >> 3) & 1) << 3);
                unsigned ad = (unsigned)__cvta_generic_to_shared(Bm + r * SSTR + kk);
                asm volatile("ldmatrix.sync.aligned.m8n8.x2.trans.shared.b16 {%0,%1}, [%2];\n"
                             : "=r"(bf[ni][0]), "=r"(bf[ni][1]) : "r"(ad));
            }
#pragma unroll
            for (int mi = 0; mi < 4; mi++)
#pragma unroll
                for (int ni = 0; ni < 4; ni++)
                    asm volatile("mma.sync.aligned.m16n8k16.row.col.f32.bf16.bf16.f32 "
                                 "{%0,%1,%2,%3},{%4,%5,%6,%7},{%8,%9},{%0,%1,%2,%3};\n"
                                 : "+f"(acc[mi][ni][0]), "+f"(acc[mi][ni][1]),
                                   "+f"(acc[mi][ni][2]), "+f"(acc[mi][ni][3])
                                 : "r"(af[mi][0]), "r"(af[mi][1]), "r"(af[mi][2]), "r"(af[mi][3]),
                                   "r"(bf[ni][0]), "r"(bf[ni][1]));
        }
    }

    // epilogue: e = exp(sim/T - 20) = exp2(acc*C - C), row-sum, deterministic partial write
#pragma unroll
    for (int mi = 0; mi < 4; mi++) {
#pragma unroll
        for (int sub = 0; sub < 2; sub++) {
            float s = 0.0f;
#pragma unroll
            for (int ni = 0; ni < 4; ni++) {
                s += ex2(fmaf(acc[mi][ni][2 * sub],     SHIFT_C, -SHIFT_C));
                s += ex2(fmaf(acc[mi][ni][2 * sub + 1], SHIFT_C, -SHIFT_C));
            }
            s += __shfl_xor_sync(0xffffffffu, s, 1);
            s += __shfl_xor_sync(0xffffffffu, s, 2);
            if ((lane & 3) == 0)
                atomicAdd(&s_row[wm * 64 + mi * 16 + sub * 8 + (lane >> 2)], s);
        }
    }
    __syncthreads();
    if (tid < BM)
        g_part[(size_t)(rowBase + tid) * NYT + blockIdx.y] = s_row[tid];
}

// ---------------- kernel 4: reduce partials -> lse ----------------
__global__ void k_reduce() {
    int w = (blockIdx.x * blockDim.x + threadIdx.x) >> 5;
    int lane = threadIdx.x & 31;
    if (w >= NB) return;
    const float* sp = g_part + (size_t)w * NYT;
    float s = 0.0f;
#pragma unroll
    for (int j = 0; j < NYT / 32; j++) s += sp[lane + 32 * j];
    s = wredsum(s);
    if (lane == 0) g_lse[w] = logf(s) + 20.0f;
}

// ---------------- kernel 5: finalize (single block, deterministic) ----------------
__global__ void k_final(const int* __restrict__ cnt, float* __restrict__ out) {
    float local = 0.0f;
    for (int b = threadIdx.x; b < NB; b += 256) {
        float lse = g_lse[b];
        int c = cnt[b];
        float ps[NP];
#pragma unroll
        for (int j = 0; j < NP; j++) ps[j] = g_pos[b * NP + j];

        float m = ps[0];
#pragma unroll
        for (int j = 1; j < NP; j++) m = fmaxf(m, ps[j]);
        float Z = 0.0f, W = 0.0f;
#pragma unroll
        for (int j = 0; j < NP; j++) {
            float w = __expf(ps[j] - m);
            Z += w;
            W += w * ps[j];
        }
        float wps = W / Z;

#pragma unroll
        for (int j = 0; j < NP; j++)
            if (j < c) local += logaddexp_(ps[j], lse) - ps[j];
        if (c > 1) local += 0.1f * (logaddexp_(wps, lse) - wps);
    }

    __shared__ float red[256];
    red[threadIdx.x] = local;
    __syncthreads();
#pragma unroll
    for (int o = 128; o; o >>= 1) {
        if (threadIdx.x < o) red[threadIdx.x] += red[threadIdx.x + o];
        __syncthreads();
    }
    if (threadIdx.x == 0) out[0] = red[0] / (float)NB;
}

// ---------------- launch ----------------
extern "C" void kernel_launch(void* const* d_in, const int* in_sizes, int n_in,
                              void* d_out, int out_size) {
    const float* a = (const float*)d_in[0];
    const float* p = (const float*)d_in[1];
    const float* n = (const float*)d_in[2];
    const int* cnt = (const int*)d_in[3];

    k_norm_anchor<<<NB / 8, 256>>>(a, p);
    k_norm_neg<<<NN / 8, 256>>>(n);
    k_gemm<<<dim3(NB / BM, NYT), 256>>>();
    k_reduce<<<NB / 8, 256>>>();
    k_final<<<1, 256>>>(cnt, (float*)d_out);
}